// round 16
// baseline (speedup 1.0000x reference)
#include <cuda_runtime.h>
#include <cuda_fp16.h>
#include <math.h>

#define PI_F 3.14159f

// Scratch: __device__ globals (no allocation allowed)
__device__ float g_p[4 * 256];        // relu(pc @ W1 + b1)
__device__ float g_par[4 * 256 * 4];  // per (b,c): m0, m1, tx, ty
__device__ int g_cnt1 = 0;            // mlp1 completion counter (self-resetting)
__device__ int g_cnt2 = 0;            // mlp2 completion counter (self-resetting)
__device__ int g_fin  = 0;            // block finish counter (self-resetting)

static constexpr int PSH = 136;                  // half2 pairs per row (544 B)
static constexpr int SROWS = 131;                // rows -1 .. 129
static constexpr int OFF = 4;                    // interior texel 0 -> pair idx 4
static constexpr int PLANE_BYTES = SROWS * PSH * 4;   // 71264

// Single fused kernel. Blocks 0..63 additionally compute the MLPs (wide,
// coalesced) before their own tile; everyone else starts plane loads
// immediately and only waits for g_par AFTER the plane barrier, by which
// time the MLP flag is long set. Flag counters self-reset at kernel end so
// every graph replay sees a clean state.
__global__ __launch_bounds__(512, 3)
void fused_kernel(const float* __restrict__ fm, float* __restrict__ out,
                  const float* __restrict__ pc,
                  const float* __restrict__ W1, const float* __restrict__ b1,
                  const float* __restrict__ Ws, const float* __restrict__ bs,
                  const float* __restrict__ Wr, const float* __restrict__ br,
                  const float* __restrict__ Wt, const float* __restrict__ bt) {
    extern __shared__ __align__(16) char smx[];
    __half2* P = (__half2*)smx;

    int bc = blockIdx.x;
    int b = bc >> 8;
    int c = bc & 255;
    int tid = threadIdx.x;

    // ================= producer blocks: MLP stages in smem scratch =========
    if (bc < 64) {
        float*  s     = (float*)smx;              // 256 floats
        float*  part  = (float*)smx + 256;        // 256 floats (mlp1 partials)
        float4* part4 = (float4*)((float*)smx + 512);  // 256 float4 (mlp2)
        int bb  = bc >> 4;           // batch
        int grp = bc & 15;           // output group (16 j's / 16 c's)
        int jl = tid & 15;
        int q  = tid >> 4;           // 0..15 for tid<256

        if (tid < 256) s[tid] = pc[bb * 256 + tid];
        __syncthreads();
        if (tid < 256) {             // mlp1: 16 outputs x 16 k-slices
            float acc = 0.0f;
            int k0 = q * 16;
            int j = grp * 16 + jl;
#pragma unroll
            for (int i = 0; i < 16; i++)
                acc = fmaf(s[k0 + i], W1[(k0 + i) * 256 + j], acc);
            part[tid] = acc;
        }
        __syncthreads();
        if (tid < 16) {
            float a = b1[grp * 16 + tid];
#pragma unroll
            for (int qq = 0; qq < 16; qq++) a += part[qq * 16 + tid];
            g_p[bb * 256 + grp * 16 + tid] = fmaxf(a, 0.0f);
        }
        __threadfence();             // release g_p writes
        __syncthreads();
        if (tid == 0) {
            atomicAdd(&g_cnt1, 1);
            while (atomicAdd(&g_cnt1, 0) < 64) __nanosleep(100);
        }
        __syncthreads();
        // stage full g_p[bb] into smem (L2-coherent read)
        if (tid < 256) s[tid] = __ldcg(&g_p[bb * 256 + tid]);
        __syncthreads();
        if (tid < 256) {             // mlp2: 16 channels x 16 k-slices
            int cch = grp * 16 + jl;
            float as = 0.f, ar = 0.f, at0 = 0.f, at1 = 0.f;
            int k0 = q * 16;
#pragma unroll
            for (int i = 0; i < 16; i++) {
                int row = k0 + i;
                float pv = s[row];
                as  = fmaf(pv, Ws[row * 256 + cch], as);
                ar  = fmaf(pv, Wr[row * 256 + cch], ar);
                at0 = fmaf(pv, Wt[row * 512 + 2 * cch], at0);
                at1 = fmaf(pv, Wt[row * 512 + 2 * cch + 1], at1);
            }
            part4[tid] = make_float4(as, ar, at0, at1);
        }
        __syncthreads();
        if (tid < 16) {
            int cc = grp * 16 + tid;
            float a0 = bs[cc], a1 = br[cc], a2 = bt[2 * cc], a3 = bt[2 * cc + 1];
#pragma unroll
            for (int qq = 0; qq < 16; qq++) {
                float4 v = part4[qq * 16 + tid];
                a0 += v.x; a1 += v.y; a2 += v.z; a3 += v.w;
            }
            float scale = 2.0f / (1.0f + expf(-a0));
            float angle = tanhf(a1) * PI_F;
            float4 o;
            o.x = scale * cosf(angle);
            o.y = scale * sinf(angle);
            o.z = tanhf(a2);
            o.w = tanhf(a3);
            *(float4*)&g_par[(bb * 256 + cc) * 4] = o;
        }
        __threadfence();             // release g_par writes
        __syncthreads();
        if (tid == 0) atomicAdd(&g_cnt2, 1);
        __syncthreads();             // smem free for plane reuse
    }

    // ================= every block: plane load + sampling ==================
    // z coordinate: iz = 128*zc + 127.5, zc = 2*c/255 - 1
    float zc = fmaf(2.0f / 255.0f, (float)c, -1.0f);
    float iz = fmaf(zc, 128.0f, 127.5f);
    float z0f = floorf(iz);
    float wz = iz - z0f;
    float wza = 1.0f - wz;
    int z0 = (int)z0f;
    int z1 = z0 + 1;
    bool v0 = ((unsigned)z0 < 256u);
    bool v1 = ((unsigned)z1 < 256u);

    const float* base = fm + (size_t)b * (256 * 128 * 128);
    const float4* p0 = (const float4*)(base + (size_t)(v0 ? z0 : 0) * 16384);
    const float4* p1 = (const float4*)(base + (size_t)(v1 ? z1 : 0) * 16384);

    // border zeroing: rows 0,129,130 fully (34 uint4 each = 102 threads) +
    // right pair col for rows 1..128 (128 threads). 230 total; disjoint from
    // interior writes.
    if (tid < 230) {
        if (tid < 102) {
            int r = tid / 34;                 // 0..2
            int row = (r == 0) ? 0 : (128 + r);
            int col = tid - r * 34;           // 0..33 (uint4 units)
            *(uint4*)((char*)P + (size_t)row * PSH * 4 + col * 16) =
                make_uint4(0, 0, 0, 0);
        } else {
            int r = tid - 101;                // 1..128
            P[r * PSH + OFF + 128] = __float2half2_rn(0.0f);
        }
    }

    // load interior 128x128, blend in fp32, pack to duplicated half2 pairs:
    // P[row][j] = (h(v[j]), h(v[j+1])) -> one LDS.32 per bilinear tap row.
#pragma unroll
    for (int it = 0; it < 8; it++) {
        int idx = it * 512 + tid;
        int row = idx >> 5;
        int col4 = idx & 31;
        float4 a  = v0 ? p0[idx] : make_float4(0.f, 0.f, 0.f, 0.f);
        float4 bb = v1 ? p1[idx] : make_float4(0.f, 0.f, 0.f, 0.f);
        float r0 = fmaf(wza, a.x, wz * bb.x);
        float r1 = fmaf(wza, a.y, wz * bb.y);
        float r2 = fmaf(wza, a.z, wz * bb.z);
        float r3 = fmaf(wza, a.w, wz * bb.w);
        float r4 = __shfl_down_sync(0xFFFFFFFFu, r0, 1);
        if (col4 == 31) r4 = 0.0f;
        __half h0 = __float2half_rn(r0);
        __half h1 = __float2half_rn(r1);
        __half h2 = __float2half_rn(r2);
        __half h3 = __float2half_rn(r3);
        __half h4 = __float2half_rn(r4);
        __half2 q0 = __halves2half2(h0, h1);
        __half2 q1 = __halves2half2(h1, h2);
        __half2 q2 = __halves2half2(h2, h3);
        __half2 q3 = __halves2half2(h3, h4);
        uint4 pk;
        pk.x = *(unsigned int*)&q0;
        pk.y = *(unsigned int*)&q1;
        pk.z = *(unsigned int*)&q2;
        pk.w = *(unsigned int*)&q3;
        *(uint4*)((char*)P + (size_t)(row + 1) * PSH * 4 + (OFF + col4 * 4) * 4) = pk;
        if (col4 == 0)
            P[(row + 1) * PSH + OFF - 1] = __halves2half2(__float2half_rn(0.0f), h0);
    }
    __syncthreads();   // plane + border ready

    // wait for MLP params (normally already satisfied by now)
    if (tid == 0) {
        while (atomicAdd(&g_cnt2, 0) < 64) __nanosleep(100);
    }
    __syncthreads();

    float4 par = __ldcg((const float4*)&g_par[bc * 4]);
    float m0 = par.x, m1 = par.y, tx = par.z, ty = par.w;

    // Affine in index space:
    // ix = 64*gx + 63.5, gx = m0*x - m1*y + tx, x = (2/127)w - 1, y = (2/127)h - 1
    const float s2 = 2.0f / 127.0f;
    float axw = 64.0f * m0 * s2;
    float axh = -64.0f * m1 * s2;
    float cx0 = fmaf(64.0f, tx - m0 + m1, 63.5f);
    float ayw = 64.0f * m1 * s2;
    float ayh = 64.0f * m0 * s2;
    float cy0 = fmaf(64.0f, ty - m1 - m0, 63.5f);

    int w   = tid & 127;         // constant per thread across the loop
    int h0i = tid >> 7;          // 0..3; h steps by 4 each iteration
    float ix = axw * (float)w + axh * (float)h0i + cx0;
    float iy = ayw * (float)w + ayh * (float)h0i + cy0;
    float dix = 4.0f * axh;
    float diy = 4.0f * ayh;

    const __half2* SP = P + PSH + OFF;      // pair for interior (cy,cx)=(0,0)
    float* op = out + (size_t)bc * 16384 + tid;

#pragma unroll 8
    for (int k = 0; k < 32; k++) {
        // Clamp in FLOAT space BEFORE floor: out-of-range taps land entirely
        // on zero border cells with correct weights (matches zeros padding).
        float ixc = fminf(fmaxf(ix, -1.0f), 128.0f);
        float iyc = fminf(fmaxf(iy, -1.0f), 128.0f);
        int cx = __float2int_rd(ixc);       // in [-1,128]
        int cy = __float2int_rd(iyc);
        float fx = ixc - (float)cx;
        float fy = iyc - (float)cy;
        const __half2* pp = SP + cy * PSH + cx;
        float2 t = __half22float2(pp[0]);       // (v00, v01)
        float2 bo = __half22float2(pp[PSH]);    // (v10, v11)
        float top = fmaf(fx, t.y - t.x, t.x);
        float bot = fmaf(fx, bo.y - bo.x, bo.x);
        op[(size_t)k * 512] = fmaf(fy, bot - top, top);
        ix += dix;
        iy += diy;
    }

    // self-reset counters for the next graph replay (last block cleans up)
    if (tid == 0) {
        __threadfence();
        int v = atomicAdd(&g_fin, 1);
        if (v == 1023) {
            atomicExch(&g_cnt1, 0);
            atomicExch(&g_cnt2, 0);
            atomicExch(&g_fin, 0);
        }
    }
}

// ---------------- launch --------------------------------------------------
extern "C" void kernel_launch(void* const* d_in, const int* in_sizes, int n_in,
                              void* d_out, int out_size) {
    const float* feature_map = (const float*)d_in[0];  // [4,256,128,128]
    const float* para_code   = (const float*)d_in[1];  // [4,256]
    const float* W1 = (const float*)d_in[2];
    const float* b1 = (const float*)d_in[3];
    const float* Ws = (const float*)d_in[4];
    const float* bs = (const float*)d_in[5];
    const float* Wr = (const float*)d_in[6];
    const float* br = (const float*)d_in[7];
    const float* Wt = (const float*)d_in[8];
    const float* bt = (const float*)d_in[9];
    float* out = (float*)d_out;

    cudaFuncSetAttribute(fused_kernel, cudaFuncAttributeMaxDynamicSharedMemorySize,
                         PLANE_BYTES);

    fused_kernel<<<1024, 512, PLANE_BYTES>>>(feature_map, out, para_code,
                                             W1, b1, Ws, bs, Wr, br, Wt, bt);
}